// round 7
// baseline (speedup 1.0000x reference)
#include <cuda_runtime.h>
#include <math.h>

#define B 8
#define C 256
#define H 128
#define W 128
#define OH 65
#define OW 65
#define HW (H*W)          // 16384
#define OHW (OH*OW)       // 4225
#define NPIX (B*OHW)      // 33800 output pixels
#define SPLIT 8           // channel splits in norm kernel
#define CPS (C/SPLIT)     // 32 channels per split

// gather tiling
#define CPB 8             // channels per block
#define NCB (C/CPB)       // 32 channel blocks
#define OYT 4             // output rows per block
#define NYT ((OH+OYT-1)/OYT)  // 17 oy tiles
#define PAIRS 33          // ceil(OW/2)
#define IROWS (2*OYT+1)   // 9 input rows per tile
#define COLP 132          // padded smem row (floats), %4==0

// Scratch: device globals (no allocation allowed)
__device__ float g_part[SPLIT*B*HW];     // 4 MB, partial sum-of-squares
__device__ float g_norm[B*HW];           // 512 KB
__device__ float g_wts[9*NPIX];          // ~1.22 MB, layout [k][b][oy][ox]

// ---------------------------------------------------------------------------
// Kernel 1: partial channel sum-of-squares, float4 loads, 8-way channel split.
// ---------------------------------------------------------------------------
__global__ __launch_bounds__(128) void norm_part_kernel(const float* __restrict__ x) {
    int t   = threadIdx.x;
    int w4  = t & 31;
    int hl  = t >> 5;
    int bh4 = blockIdx.x;
    int b   = bh4 >> 5;
    int h   = ((bh4 & 31) << 2) + hl;
    int c0  = blockIdx.y * CPS;

    const float4* p = (const float4*)(x + ((size_t)(b * C + c0)) * HW + (size_t)h * W) + w4;

    float sx = 0.f, sy = 0.f, sz = 0.f, sw = 0.f;
    #pragma unroll 8
    for (int c = 0; c < CPS; c++) {
        float4 v = p[(size_t)c * (HW / 4)];
        sx = fmaf(v.x, v.x, sx);
        sy = fmaf(v.y, v.y, sy);
        sz = fmaf(v.z, v.z, sz);
        sw = fmaf(v.w, v.w, sw);
    }

    float4 o = make_float4(sx, sy, sz, sw);
    ((float4*)g_part)[(size_t)blockIdx.y * (B * HW / 4) + ((size_t)(b * H + h) * W) / 4 + w4] = o;
}

// ---------------------------------------------------------------------------
// Kernel 2: reduce partials + sqrt -> g_norm.
// ---------------------------------------------------------------------------
__global__ __launch_bounds__(256) void norm_reduce_kernel() {
    int i = blockIdx.x * blockDim.x + threadIdx.x;
    if (i >= B * HW / 4) return;
    const float4* p = (const float4*)g_part;
    float4 a = p[i];
    #pragma unroll
    for (int s = 1; s < SPLIT; s++) {
        float4 v = p[(size_t)s * (B * HW / 4) + i];
        a.x += v.x; a.y += v.y; a.z += v.z; a.w += v.w;
    }
    a.x = sqrtf(a.x); a.y = sqrtf(a.y); a.z = sqrtf(a.z); a.w = sqrtf(a.w);
    ((float4*)g_norm)[i] = a;
}

// ---------------------------------------------------------------------------
// Kernel 3: softmax weights over 3x3 window of norms (zero-padded).
// ---------------------------------------------------------------------------
__global__ __launch_bounds__(256) void wts_kernel() {
    int idx = blockIdx.x * blockDim.x + threadIdx.x;
    if (idx >= NPIX) return;
    int ox = idx % OW;
    int t  = idx / OW;
    int oy = t % OH;
    int b  = t / OH;

    int iy0 = 2 * oy - 2;
    int ix0 = 2 * ox - 2;

    float v[9];
    #pragma unroll
    for (int i = 0; i < 3; i++) {
        int iy = iy0 + i;
        bool rok = (unsigned)iy < (unsigned)H;
        #pragma unroll
        for (int j = 0; j < 3; j++) {
            int ix = ix0 + j;
            bool ok = rok && ((unsigned)ix < (unsigned)W);
            v[i * 3 + j] = ok ? g_norm[(b * H + iy) * W + ix] : 0.f;
        }
    }

    float m = v[0];
    #pragma unroll
    for (int k = 1; k < 9; k++) m = fmaxf(m, v[k]);

    float e[9];
    float sum = 0.f;
    #pragma unroll
    for (int k = 0; k < 9; k++) {
        e[k] = expf(v[k] - m);
        sum += e[k];
    }
    float inv = 1.f / sum;

    #pragma unroll
    for (int k = 0; k < 9; k++) g_wts[k * NPIX + idx] = e[k] * inv;
}

// ---------------------------------------------------------------------------
// Kernel 4: smem-tiled gather. Block = (b, 8-channel group, 4-output-row tile).
// Phase 1: dense coalesced float4 load of 9 input rows x 128 cols x 8 ch.
// Phase 2: paired-pixel compute from smem.
// ---------------------------------------------------------------------------
__global__ __launch_bounds__(128) void gather_kernel(const float* __restrict__ x,
                                                     float* __restrict__ out) {
    __shared__ float sm[CPB][IROWS][COLP];   // 38,016 B

    int bid = blockIdx.x;
    int yt  = bid % NYT;
    int t2  = bid / NYT;
    int cgb = t2 % NCB;
    int b   = t2 / NCB;

    int oy0 = yt * OYT;
    int gy0 = 2 * oy0 - 2;
    int tid = threadIdx.x;

    // ---- Phase 1: dense coalesced load ----
    const float* xb = x + (size_t)(b * C + cgb * CPB) * HW;
    #pragma unroll
    for (int i = 0; i < (IROWS * CPB * 32) / 128; i++) {   // 18 iters
        int li   = i * 128 + tid;
        int col4 = li & 31;
        int ch   = (li >> 5) & 7;
        int row  = li >> 8;                  // 0..8
        int gy   = gy0 + row;
        gy = gy < 0 ? 0 : (gy >= H ? H - 1 : gy);
        float4 v = *(const float4*)(xb + (size_t)ch * HW + gy * W + col4 * 4);
        *(float4*)&sm[ch][row][col4 * 4] = v;
    }
    __syncthreads();

    // ---- Phase 2: compute ----
    for (int s = tid; s < OYT * PAIRS; s += 128) {
        int p   = s % PAIRS;
        int oyl = s / PAIRS;
        int oy  = oy0 + oyl;
        if (oy >= OH) continue;

        int ox0  = 2 * p;
        bool has1 = (p < PAIRS - 1);

        int pix0 = (b * OH + oy) * OW + ox0;
        float w0[9], w1[9];
        #pragma unroll
        for (int k = 0; k < 9; k++) {
            w0[k] = g_wts[k * NPIX + pix0];
            w1[k] = has1 ? g_wts[k * NPIX + pix0 + 1] : 0.f;
        }

        int baseA = 4 * p - 2;
        if (p == 0) {
            baseA = 0;
            w0[0] = w0[1] = 0.f; w0[3] = w0[4] = 0.f; w0[6] = w0[7] = 0.f;
        }
        int baseB = 4 * p;
        if (baseB > W - 4) {
            baseB = W - 4;
            w0[2] = w0[5] = w0[8] = 0.f;
        }

        int lr[3];
        #pragma unroll
        for (int i = 0; i < 3; i++) {
            int iy = 2 * oy - 2 + i;
            lr[i] = 2 * oyl + i;
            if (iy < 0 || iy >= H) {
                w0[i*3] = w0[i*3+1] = w0[i*3+2] = 0.f;
                w1[i*3] = w1[i*3+1] = w1[i*3+2] = 0.f;
            }
        }

        float acc0[CPB], acc1[CPB];
        #pragma unroll
        for (int c = 0; c < CPB; c++) { acc0[c] = 0.f; acc1[c] = 0.f; }

        #pragma unroll
        for (int i = 0; i < 3; i++) {
            float a0 = w0[i*3], a1 = w0[i*3+1], a2 = w0[i*3+2];
            float b0 = w1[i*3], b1 = w1[i*3+1], b2 = w1[i*3+2];
            #pragma unroll
            for (int c = 0; c < CPB; c++) {
                float2 A2 = *(const float2*)&sm[c][lr[i]][baseA];
                float4 Bv = *(const float4*)&sm[c][lr[i]][baseB];
                acc0[c] = fmaf(a0, A2.x, acc0[c]);
                acc0[c] = fmaf(a1, A2.y, acc0[c]);
                acc0[c] = fmaf(a2, Bv.x, acc0[c]);
                acc1[c] = fmaf(b0, Bv.x, acc1[c]);
                acc1[c] = fmaf(b1, Bv.y, acc1[c]);
                acc1[c] = fmaf(b2, Bv.z, acc1[c]);
            }
        }

        float* op = out + ((size_t)(b * C + cgb * CPB) * OH + oy) * OW + ox0;
        #pragma unroll
        for (int c = 0; c < CPB; c++) {
            op[(size_t)c * OHW] = acc0[c];
            if (has1) op[(size_t)c * OHW + 1] = acc1[c];
        }
    }
}

// ---------------------------------------------------------------------------
extern "C" void kernel_launch(void* const* d_in, const int* in_sizes, int n_in,
                              void* d_out, int out_size) {
    const float* x = (const float*)d_in[0];
    float* out = (float*)d_out;

    dim3 g1(B * H / 4, SPLIT);                   // 2048 blocks
    norm_part_kernel<<<g1, 128>>>(x);

    int n2 = B * HW / 4;
    norm_reduce_kernel<<<(n2 + 255) / 256, 256>>>();

    wts_kernel<<<(NPIX + 255) / 256, 256>>>();

    int n4 = B * NCB * NYT;                      // 8*32*17 = 4352 blocks
    gather_kernel<<<n4, 128>>>(x, out);
}